// round 7
// baseline (speedup 1.0000x reference)
#include <cuda_runtime.h>
#include <cstdint>

#define MAX_E 100000
#define MAX_T 1000000
#define CCH   64
#define SCAN_BLK 512
#define MAX_SCAN_BLOCKS ((MAX_E + SCAN_BLK - 1) / SCAN_BLK)
#define TPW   128                       // CSR slots per window/block
#define RS    65                        // padded smem row stride (odd => conflict-free)
#define NB_MAX (MAX_T / TPW + 3)

// Scratch (device globals — zero at module load; every run self-restores the
// arrays that must be zero on entry: g_cnt/g_cursor via k_fix, g_acc/g_aden too).
__device__ float4   g_rnorm4[MAX_E];
__device__ unsigned g_cnt[MAX_E];
__device__ unsigned g_off[MAX_E];
__device__ unsigned g_cursor[MAX_E];
__device__ unsigned g_bsum[MAX_SCAN_BLOCKS];
__device__ int4     g_pack[MAX_T];      // {src, dst, cos_theta bits, 0} CSR-ordered
__device__ int      g_bstart[NB_MAX];   // first edge with off >= b*TPW
__device__ float    g_acc[(size_t)MAX_E * CCH];  // partial sums (boundary edges)
__device__ float    g_aden[MAX_E];

// ---------------------------------------------------------------------------
__global__ void k_prep_count(const float* __restrict__ r,
                             const int* __restrict__ tdst, int E, int T) {
    int i = blockIdx.x * blockDim.x + threadIdx.x;
    if (i < E) {
        float x = r[3 * i + 0], y = r[3 * i + 1], z = r[3 * i + 2];
        float inv = rsqrtf(x * x + y * y + z * z);
        g_rnorm4[i] = make_float4(x * inv, y * inv, z * inv, 0.0f);
    }
    if (i < T) atomicAdd(&g_cnt[tdst[i]], 1u);
}

// --------------------------- exclusive scan --------------------------------
__global__ void k_scan1(int E) {
    __shared__ unsigned sh[SCAN_BLK];
    int i = blockIdx.x * SCAN_BLK + threadIdx.x;
    unsigned v = (i < E) ? g_cnt[i] : 0u;
    sh[threadIdx.x] = v;
    __syncthreads();
    unsigned incl = v;
    for (int ofs = 1; ofs < SCAN_BLK; ofs <<= 1) {
        unsigned add = (threadIdx.x >= ofs) ? sh[threadIdx.x - ofs] : 0u;
        __syncthreads();
        incl += add;
        sh[threadIdx.x] = incl;
        __syncthreads();
    }
    if (i < E) g_off[i] = incl - v;
    if (threadIdx.x == SCAN_BLK - 1) g_bsum[blockIdx.x] = incl;
}

__global__ void k_scan2(int nb) {
    __shared__ unsigned sh[SCAN_BLK];
    unsigned v = (threadIdx.x < nb) ? g_bsum[threadIdx.x] : 0u;
    sh[threadIdx.x] = v;
    __syncthreads();
    unsigned incl = v;
    for (int ofs = 1; ofs < SCAN_BLK; ofs <<= 1) {
        unsigned add = (threadIdx.x >= ofs) ? sh[threadIdx.x - ofs] : 0u;
        __syncthreads();
        incl += add;
        sh[threadIdx.x] = incl;
        __syncthreads();
    }
    if (threadIdx.x < nb) g_bsum[threadIdx.x] = incl - v;
}

__global__ void k_scan3(int E) {
    int i = blockIdx.x * SCAN_BLK + threadIdx.x;
    if (i < E) g_off[i] += g_bsum[blockIdx.x];
}

// ---------------------------------------------------------------------------
// bstart[b] = first edge e with off[e] >= b*TPW  (E if none)
// ---------------------------------------------------------------------------
__global__ void k_bstart(int E, int T, int nb) {
    int e = blockIdx.x * blockDim.x + threadIdx.x;
    if (e >= E) return;
    int be = (int)g_off[e] / TPW;
    int bp = (e == 0) ? -1 : (int)g_off[e - 1] / TPW;
    for (int b = bp + 1; b <= be; b++) g_bstart[b] = e;
    if (e == E - 1)
        for (int b = be + 1; b <= nb; b++) g_bstart[b] = E;
}

// ---------------------------------------------------------------------------
// perm: CSR scatter of packed {src, dst, cos(theta)} per slot (one STG.128)
// ---------------------------------------------------------------------------
__global__ void k_perm(const int* __restrict__ tsrc, const int* __restrict__ tdst, int T) {
    int t = blockIdx.x * blockDim.x + threadIdx.x;
    if (t >= T) return;
    int s = tsrc[t], d = tdst[t];
    unsigned pos = g_off[d] + atomicAdd(&g_cursor[d], 1u);
    float4 rs = __ldg(&g_rnorm4[s]);
    float4 rd = __ldg(&g_rnorm4[d]);
    float cth = rs.x * rd.x + rs.y * rd.y + rs.z * rd.z;
    cth = fminf(fmaxf(cth, -1.0f + 1e-6f), 1.0f - 1e-6f);
    g_pack[pos] = make_int4(s, d, __float_as_int(cth), 0);
}

// ---------------------------------------------------------------------------
// fused: per 128-slot CSR window (34KB smem -> 6 CTAs/SM).
//  A) stage src rows to smem (coalesced, padded odd stride 65)
//  B) thread-per-slot logit + exp (Chebyshev recurrence; softmax without max
//     subtraction — |logit| << 88, alpha identical; validated R4/R5)
//  C) warp-per-edge aggregate from smem, lane owns channels {lane, lane+32}
//     (scalar LDS, conflict-free with odd stride):
//     full-in-window edges -> direct ft store; boundary edges -> red partials
// ---------------------------------------------------------------------------
__global__ void __launch_bounds__(TPW)
k_fused(const float* __restrict__ xij, const float* __restrict__ attn,
        float* __restrict__ ft, int E, int T) {
    __shared__ float srows[TPW * RS];
    __shared__ float sex[TPW];
    __shared__ float sat[CCH];

    int tid = threadIdx.x, lane = tid & 31, w = tid >> 5;
    int wlo = blockIdx.x * TPW;
    int n = T - wlo; if (n > TPW) n = TPW;
    int whi = wlo + n;
    if (tid < CCH) sat[tid] = attn[tid];

    // A: stage src rows
    for (int j = w; j < n; j += TPW / 32) {
        int s = __ldg(&g_pack[wlo + j].x);
        float2 v = __ldg((const float2*)(xij + (size_t)s * CCH) + lane);
        srows[j * RS + 2 * lane]     = v.x;
        srows[j * RS + 2 * lane + 1] = v.y;
    }
    __syncthreads();

    // B: logits + exp
    if (tid < n) {
        int4 p = __ldg(&g_pack[wlo + tid]);
        int d = p.y;
        float cth = __int_as_float(p.z);
        float c2 = 2.0f * cth;
        float zp = cth, zc = 1.0f;     // T_{-1}, T_0

        const float4* xd = (const float4*)(xij + (size_t)d * CCH);
        const float* row = &srows[tid * RS];
        float a = 0.0f;
#pragma unroll
        for (int k = 0; k < CCH / 4; k++) {
            float4 D = __ldg(xd + k);
            float dv[4] = {D.x, D.y, D.z, D.w};
#pragma unroll
            for (int q = 0; q < 4; q++) {
                int c = 4 * k + q;
                float v = zc + row[c] + dv[q];
                float e = __fdividef(v, 1.0f + __expf(-v));   // silu
                a = fmaf(e, sat[c], a);
                float zn = fmaf(c2, zc, -zp);                 // Chebyshev
                zp = zc; zc = zn;
            }
        }
        sex[tid] = __expf(a);
    }
    __syncthreads();

    // C: warp-per-edge aggregate (lane -> channels lane, lane+32)
    int e0 = g_bstart[blockIdx.x];
    if (e0 >= E) e0 = E - 1;
    else if (e0 > 0 && (int)g_off[e0] > wlo) e0--;   // edge containing slot wlo

    for (int e = e0 + w; e < E; e += TPW / 32) {
        int o = (int)__ldg(&g_off[e]);
        if (o >= whi) break;
        int on = (e + 1 < E) ? (int)__ldg(&g_off[e + 1]) : T;
        int lo = (o > wlo ? o : wlo) - wlo;
        int hi = (on < whi ? on : whi) - wlo;

        float ax = 0.0f, ay = 0.0f, den = 0.0f;
        for (int i = lo; i < hi; i++) {
            float ex = sex[i];
            float vx = srows[i * RS + lane];
            float vy = srows[i * RS + 32 + lane];
            den += ex;
            ax = fmaf(ex, vx, ax);
            ay = fmaf(ex, vy, ay);
        }

        bool full = (o >= wlo) && (on <= whi);
        if (full) {
            float inv = (hi > lo) ? __fdividef(1.0f, den) : 0.0f;
            ft[(size_t)e * CCH + lane]      = ax * inv;
            ft[(size_t)e * CCH + 32 + lane] = ay * inv;
        } else if (hi > lo) {
            float* dst = g_acc + (size_t)e * CCH;
            asm volatile("red.global.add.f32 [%0], %1;"
                         :: "l"(dst + lane), "f"(ax) : "memory");
            asm volatile("red.global.add.f32 [%0], %1;"
                         :: "l"(dst + 32 + lane), "f"(ay) : "memory");
            if (lane == 0) atomicAdd(&g_aden[e], den);
        }
    }
}

// ---------------------------------------------------------------------------
// fix: finish boundary edges (ft = acc/den), zero-fill deg-0 edges,
// and restore all scratch to zero for the next run.
// ---------------------------------------------------------------------------
__global__ void __launch_bounds__(256)
k_fix(float* __restrict__ ft, int E) {
    int warp = (blockIdx.x * blockDim.x + threadIdx.x) >> 5;
    int lane = threadIdx.x & 31;
    if (warp >= E) return;

    float den = g_aden[warp];
    unsigned cnt = g_cnt[warp];
    if (lane == 0) { g_cnt[warp] = 0u; g_cursor[warp] = 0u; }

    if (den != 0.0f) {
        float inv = __fdividef(1.0f, den);
        float* arow = g_acc + (size_t)warp * CCH;
        float vx = arow[lane], vy = arow[32 + lane];
        ft[(size_t)warp * CCH + lane]      = vx * inv;
        ft[(size_t)warp * CCH + 32 + lane] = vy * inv;
        arow[lane] = 0.0f;
        arow[32 + lane] = 0.0f;
        if (lane == 0) g_aden[warp] = 0.0f;
    } else if (cnt == 0u) {
        ft[(size_t)warp * CCH + lane]      = 0.0f;
        ft[(size_t)warp * CCH + 32 + lane] = 0.0f;
    }
}

// ---------------------------------------------------------------------------
extern "C" void kernel_launch(void* const* d_in, const int* in_sizes, int n_in,
                              void* d_out, int out_size) {
    const float* xij  = (const float*)d_in[0];
    const float* r    = (const float*)d_in[1];
    const float* attn = (const float*)d_in[2];
    const int*   tsrc = (const int*)d_in[3];
    const int*   tdst = (const int*)d_in[4];
    float* ft = (float*)d_out;

    int E = in_sizes[1] / 3;
    int T = in_sizes[3];
    int nsb = (E + SCAN_BLK - 1) / SCAN_BLK;
    int nb  = (T + TPW - 1) / TPW;
    int nmx = (T > E) ? T : E;

    k_prep_count<<<(nmx + 255) / 256, 256>>>(r, tdst, E, T);
    k_scan1 <<<nsb, SCAN_BLK>>>(E);
    k_scan2 <<<1,   SCAN_BLK>>>(nsb);
    k_scan3 <<<nsb, SCAN_BLK>>>(E);
    k_bstart<<<(E + 255) / 256, 256>>>(E, T, nb);
    k_perm  <<<(T + 255) / 256, 256>>>(tsrc, tdst, T);
    k_fused <<<nb, TPW>>>(xij, attn, ft, E, T);
    k_fix   <<<(E * 32 + 255) / 256, 256>>>(ft, E);
}